// round 1
// baseline (speedup 1.0000x reference)
#include <cuda_runtime.h>
#include <math.h>
#include <stdint.h>

#define NN 200000
#define KK 64
#define Q_MIN 0.1f

// ---------------- device globals (scratch; no allocation allowed) ----------------
__device__ unsigned long long g_key[KK];   // packed argmax key per object
__device__ float g_pwden[KK];              // sum of b per object
__device__ int   g_cnt[KK];                // hits per object
__device__ float g_noise_b;                // sum b * is_noise
__device__ int   g_noise_n;                // count noise
__device__ float g_ax[KK], g_ay[KK];       // alpha coords
__device__ float g_qv[KK];                 // q_alpha * valid
__device__ float g_invpw[KK];              // valid / (pw_den + 1e-9)
__device__ float g_nvalid;                 // max(sum valid, 1)
__device__ float g_beta_alpha;             // sum (1 - b_alpha) * valid
__device__ double g_acc[6];                // att, rep, LE, Lpos, Lt, Lcls

// ---------------- helpers ----------------
__device__ __forceinline__ float clipb(float b) {
    return fminf(fmaxf(b, 1e-6f), 1.0f - 1e-6f);
}
__device__ __forceinline__ float huberf(float x, float d) {
    float ax = fabsf(x);
    return (ax < d) ? x * x : (d * d + 2.0f * d * (ax - d));
}
__device__ __forceinline__ float softclipf(float x, float s) {
    float y = x / s;
    y = (y > 1.0f) ? logf(y + 1.0f) : y;
    return y * s;
}
__device__ __forceinline__ float sqrt_approx(float x) {
    float r;
    asm("sqrt.approx.f32 %0, %1;" : "=f"(r) : "f"(x));
    return r;
}

// ---------------- kernel 0: init ----------------
__global__ void k_init() {
    int t = threadIdx.x;
    if (t < KK) { g_key[t] = 0ull; g_pwden[t] = 0.0f; g_cnt[t] = 0; }
    if (t == 0) { g_noise_b = 0.0f; g_noise_n = 0; }
    if (t < 6)  g_acc[t] = 0.0;
}

// ---------------- kernel 1: per-object argmax / sums + noise ----------------
__global__ void k_pass1(const float* __restrict__ beta, const int* __restrict__ tidx) {
    __shared__ unsigned long long s_key[KK];
    __shared__ float s_pw[KK];
    __shared__ int   s_cnt[KK];
    __shared__ float s_nb[8];
    __shared__ int   s_nn[8];

    int t = threadIdx.x;
    if (t < KK) { s_key[t] = 0ull; s_pw[t] = 0.0f; s_cnt[t] = 0; }
    __syncthreads();

    int i = blockIdx.x * blockDim.x + t;
    float nb = 0.0f; int nn = 0;
    if (i < NN) {
        int k = tidx[i];
        float b = clipb(beta[i]);
        if (k > 0) {
            int o = k - 1;
            unsigned long long key =
                ((unsigned long long)__float_as_uint(b) << 32) |
                (unsigned long long)(0xFFFFFFFFu - (unsigned)i);
            atomicMax(&s_key[o], key);
            atomicAdd(&s_pw[o], b);
            atomicAdd(&s_cnt[o], 1);
        } else {
            nb = b; nn = 1;
        }
    }
    // warp reduce noise
    #pragma unroll
    for (int off = 16; off; off >>= 1) {
        nb += __shfl_down_sync(0xffffffffu, nb, off);
        nn += __shfl_down_sync(0xffffffffu, nn, off);
    }
    int warp = t >> 5, lane = t & 31;
    if (lane == 0) { s_nb[warp] = nb; s_nn[warp] = nn; }
    __syncthreads();
    if (t == 0) {
        float tb = 0.0f; int tn = 0;
        #pragma unroll
        for (int w = 0; w < 8; w++) { tb += s_nb[w]; tn += s_nn[w]; }
        if (tn > 0) { atomicAdd(&g_noise_b, tb); atomicAdd(&g_noise_n, tn); }
    }
    if (t < KK && s_cnt[t] > 0) {
        atomicMax(&g_key[t], s_key[t]);
        atomicAdd(&g_pwden[t], s_pw[t]);
        atomicAdd(&g_cnt[t], s_cnt[t]);
    }
}

// ---------------- kernel 2: extract alpha info (1 block, 64 threads) ----------------
__global__ void k_alpha(const float* __restrict__ beta, const float* __restrict__ cc) {
    int k = threadIdx.x;
    float valid = 0.0f, bterm = 0.0f;
    if (k < KK) {
        int cnt = g_cnt[k];
        valid = (cnt > 0) ? 1.0f : 0.0f;
        unsigned ia = (cnt > 0)
            ? (0xFFFFFFFFu - (unsigned)(g_key[k] & 0xFFFFFFFFull))
            : 0u;
        float b = clipb(beta[ia]);
        float a = atanhf(b);
        g_qv[k]    = (a * a + Q_MIN) * valid;
        g_ax[k]    = cc[2 * ia];
        g_ay[k]    = cc[2 * ia + 1];
        g_invpw[k] = valid / (g_pwden[k] + 1e-9f);
        bterm = (1.0f - b) * valid;
    }
    // reduce over 2 warps
    float v = valid, bt = bterm;
    #pragma unroll
    for (int off = 16; off; off >>= 1) {
        v  += __shfl_down_sync(0xffffffffu, v, off);
        bt += __shfl_down_sync(0xffffffffu, bt, off);
    }
    __shared__ float sv[2], sb[2];
    int warp = k >> 5, lane = k & 31;
    if (lane == 0) { sv[warp] = v; sb[warp] = bt; }
    __syncthreads();
    if (k == 0) {
        g_nvalid = fmaxf(sv[0] + sv[1], 1.0f);
        g_beta_alpha = sb[0] + sb[1];
    }
}

// ---------------- kernel 3: main pass (att/rep pairs + payload) ----------------
__global__ void __launch_bounds__(256)
k_main(const float* __restrict__ beta, const float2* __restrict__ cc,
       const float* __restrict__ pred_e, const float2* __restrict__ pred_p,
       const float* __restrict__ pred_t, const float2* __restrict__ pred_id,
       const float* __restrict__ t_e, const float2* __restrict__ t_p,
       const float* __restrict__ t_t, const int* __restrict__ tidx) {
    __shared__ float sx[KK], sy[KK], sqv[KK], sinv[KK];
    int t = threadIdx.x;
    if (t < KK) { sx[t] = g_ax[t]; sy[t] = g_ay[t]; sqv[t] = g_qv[t]; sinv[t] = g_invpw[t]; }
    __syncthreads();

    int i = blockIdx.x * blockDim.x + t;
    float att = 0.0f, rep = 0.0f, aLE = 0.0f, aLp = 0.0f, aLt = 0.0f, aLc = 0.0f;

    if (i < NN) {
        int myk = tidx[i] - 1;   // -1 => noise
        float b = clipb(beta[i]);
        float a = atanhf(b);
        float q = a * a + Q_MIN;
        float2 c = cc[i];

        #pragma unroll 16
        for (int k = 0; k < KK; k++) {
            float dx = c.x - sx[k];
            float dy = c.y - sy[k];
            float d2 = fmaf(dx, dx, dy * dy);
            float qv = q * sqv[k];
            float d  = sqrt_approx(d2 + 1e-9f);
            float r  = fmaxf(1.0f - d, 0.0f);   // 0 when d2 >= 1
            bool isme = (k == myk);
            float av = isme ? d2 : 0.0f;
            float rv = isme ? 0.0f : r;
            att = fmaf(qv, av, att);
            rep = fmaf(qv, rv, rep);
        }

        if (myk >= 0) {
            float invpw = sinv[myk];            // includes valid mask
            float te = t_e[i];
            float we = (te > 10.0f) ? 1.0f : fmaxf((te - 0.5f) * (1.0f / 9.5f), 0.0f);
            float w  = b * we * invpw;

            float de = te - pred_e[i];
            float el = softclipf(de * de / (te + 1.0f), 10.0f);

            float2 tp = t_p[i], pp = pred_p[i];
            float dpx = tp.x - pp.x, dpy = tp.y - pp.y;
            float dp2 = fmaf(dpx, dpx, dpy * dpy);
            float arg = sqrtf(fmaf(dp2, 0.01f, 0.01f));
            float pl  = softclipf(huberf(arg, 10.0f), 3.0f);

            float dt = t_t[i] - pred_t[i];
            float tl = softclipf(huberf(dt, 2.0f), 6.0f);

            float2 id0 = pred_id[3 * i], id1 = pred_id[3 * i + 1], id2 = pred_id[3 * i + 2];
            float cl = (id0.x * id0.x + id0.y * id0.y +
                        id1.x * id1.x + id1.y * id1.y +
                        id2.x * id2.x + id2.y * id2.y) * (1e-8f / 6.0f);

            aLE = w * el; aLp = w * pl; aLt = w * tl; aLc = w * cl;
        }
    }

    // block reduce six scalars
    #pragma unroll
    for (int off = 16; off; off >>= 1) {
        att += __shfl_down_sync(0xffffffffu, att, off);
        rep += __shfl_down_sync(0xffffffffu, rep, off);
        aLE += __shfl_down_sync(0xffffffffu, aLE, off);
        aLp += __shfl_down_sync(0xffffffffu, aLp, off);
        aLt += __shfl_down_sync(0xffffffffu, aLt, off);
        aLc += __shfl_down_sync(0xffffffffu, aLc, off);
    }
    __shared__ float sred[8][6];
    int warp = t >> 5, lane = t & 31;
    if (lane == 0) {
        sred[warp][0] = att; sred[warp][1] = rep; sred[warp][2] = aLE;
        sred[warp][3] = aLp; sred[warp][4] = aLt; sred[warp][5] = aLc;
    }
    __syncthreads();
    if (t < 6) {
        float s = 0.0f;
        #pragma unroll
        for (int w = 0; w < 8; w++) s += sred[w][t];
        atomicAdd(&g_acc[t], (double)s);
    }
}

// ---------------- kernel 4: finalize ----------------
__global__ void k_final(float* __restrict__ out) {
    double nv = (double)g_nvalid;
    double noise_den = (g_noise_n > 0) ? (double)g_noise_n : 1.0;
    double L = (g_acc[0] + g_acc[1]) / ((double)NN * nv)     // L_att + L_rep
             + (double)g_beta_alpha / nv                      // (1-b_alpha) term
             + (double)g_noise_b / noise_den                  // S_B = 1.0
             + (g_acc[2] + g_acc[3] + g_acc[4] + g_acc[5]) / nv;  // payloads
    out[0] = (float)L;
}

// ---------------- launch ----------------
extern "C" void kernel_launch(void* const* d_in, const int* in_sizes, int n_in,
                              void* d_out, int out_size) {
    const float*  beta   = (const float*)d_in[0];
    const float*  cc     = (const float*)d_in[1];
    const float*  pred_e = (const float*)d_in[2];
    const float*  pred_p = (const float*)d_in[3];
    const float*  pred_t = (const float*)d_in[4];
    const float*  pred_i = (const float*)d_in[5];
    const float*  t_e    = (const float*)d_in[6];
    const float*  t_p    = (const float*)d_in[7];
    const float*  t_t    = (const float*)d_in[8];
    const int*    t_idx  = (const int*)d_in[9];
    float* out = (float*)d_out;

    const int threads = 256;
    const int blocks = (NN + threads - 1) / threads;

    k_init<<<1, 64>>>();
    k_pass1<<<blocks, threads>>>(beta, t_idx);
    k_alpha<<<1, 64>>>(beta, cc);
    k_main<<<blocks, threads>>>(beta, (const float2*)cc, pred_e, (const float2*)pred_p,
                                pred_t, (const float2*)pred_i, t_e, (const float2*)t_p,
                                t_t, t_idx);
    k_final<<<1, 1>>>(out);
}